// round 5
// baseline (speedup 1.0000x reference)
#include <cuda_runtime.h>
#include <cuda_bf16.h>
#include <stdint.h>

// CPQuadRankLayer via mma.sync bf16 3-term split, 512 threads, double-buffered.
// B=64, N=1024, C=4, R=64, D=O=128.
//   P_c[b][r] = sum_i x[b,n,c,i] f[c,n,r,i]
//   p = P / rms_r(P); merged = prod_c p * gain; out = merged @ fo + 0.25*sum_c x

#define NN 1024

// smem layout (bytes)
#define BUFSZ    69632          // one staging buffer: XH,XL,FH,FL (64 rows x 272B each)
#define XH       0
#define XL       17408
#define FH       34816
#define FL       52224
#define RES_OFF  139264         // res[b][o] f32: 64*128*4 = 32768
#define SS_OFF   172032         // ss[c][wr][b] f32: 4*4*64*4 = 4096
#define RINV_OFF 176128         // 64 f32
#define SMEM_BYTES 176384
// epilogue overlay (in buffer 0; safe after stage-2 MMAs complete)
#define MH_OFF   0              // merged hi: 64 rows x 144B
#define ML_OFF   9216
#define FOH_OFF  18432          // fo^T hi: 128 rows x 144B
#define FOL_OFF  36864

__device__ __forceinline__ void split2(float a, float b, uint32_t& hi, uint32_t& lo) {
    __nv_bfloat16 ah = __float2bfloat16(a), bh = __float2bfloat16(b);
    hi = ((uint32_t)__bfloat16_as_ushort(bh) << 16) | (uint32_t)__bfloat16_as_ushort(ah);
    __nv_bfloat16 al = __float2bfloat16(a - __bfloat162float(ah));
    __nv_bfloat16 bl = __float2bfloat16(b - __bfloat162float(bh));
    lo = ((uint32_t)__bfloat16_as_ushort(bl) << 16) | (uint32_t)__bfloat16_as_ushort(al);
}

__device__ __forceinline__ void mma_bf16(float* c, const uint32_t* a, const uint32_t* b) {
    asm volatile(
        "mma.sync.aligned.m16n8k16.row.col.f32.bf16.bf16.f32 "
        "{%0,%1,%2,%3}, {%4,%5,%6,%7}, {%8,%9}, {%0,%1,%2,%3};"
        : "+f"(c[0]), "+f"(c[1]), "+f"(c[2]), "+f"(c[3])
        : "r"(a[0]), "r"(a[1]), "r"(a[2]), "r"(a[3]), "r"(b[0]), "r"(b[1]));
}

__global__ __launch_bounds__(512, 1)
void cpquad_mma2(const float* __restrict__ x, const float* __restrict__ f,
                 const float* __restrict__ fo, const float* __restrict__ gain,
                 float* __restrict__ out)
{
    extern __shared__ char sm[];
    const int n = blockIdx.x;
    const int t = threadIdx.x;
    const int lane = t & 31, wid = t >> 5;
    const int g = lane >> 2, tg = lane & 3;
    const int wb = wid >> 2, wr = wid & 3;      // b-tile (16 rows), r/o-tile (16 r | 32 o)
    const int bb = wb * 16;
    const int row = t >> 3, q = t & 7;          // staging: row 0-63, 16-float col chunk
    const float gn = __ldg(&gain[n]);

    float4 xr[4], fr[4], resacc[4];
    float fov[16];
    float acc[4][2][4];
#pragma unroll
    for (int c = 0; c < 4; ++c)
#pragma unroll
        for (int nt = 0; nt < 2; ++nt)
#pragma unroll
            for (int u = 0; u < 4; ++u) acc[c][nt][u] = 0.0f;

    // prologue LDG c=0
#pragma unroll
    for (int j = 0; j < 4; ++j) {
        xr[j] = *(const float4*)(x + (((size_t)row * NN + n) * 4 + 0) * 128 + q * 16 + j * 4);
        fr[j] = *(const float4*)(f + (((size_t)0 * NN + n) * 64 + row) * 128 + q * 16 + j * 4);
    }

#pragma unroll
    for (int c = 0; c < 4; ++c) {
        char* buf = sm + (c & 1) * BUFSZ;
        // STS hi/lo split + residual accumulation
#pragma unroll
        for (int j = 0; j < 4; ++j) {
            uint2 hi, lo;
            split2(xr[j].x, xr[j].y, hi.x, lo.x);
            split2(xr[j].z, xr[j].w, hi.y, lo.y);
            *(uint2*)(buf + XH + row * 272 + q * 32 + j * 8) = hi;
            *(uint2*)(buf + XL + row * 272 + q * 32 + j * 8) = lo;
            split2(fr[j].x, fr[j].y, hi.x, lo.x);
            split2(fr[j].z, fr[j].w, hi.y, lo.y);
            *(uint2*)(buf + FH + row * 272 + q * 32 + j * 8) = hi;
            *(uint2*)(buf + FL + row * 272 + q * 32 + j * 8) = lo;
            if (c == 0) resacc[j] = xr[j];
            else {
                resacc[j].x += xr[j].x; resacc[j].y += xr[j].y;
                resacc[j].z += xr[j].z; resacc[j].w += xr[j].w;
            }
        }
        if (c == 3) {
#pragma unroll
            for (int j = 0; j < 4; ++j)
                *(float4*)(sm + RES_OFF + row * 512 + q * 64 + j * 16) = resacc[j];
        }
        __syncthreads();   // buf[c&1] ready; also guarantees MMA(c-2) done (overwrite-safe)

        // prefetch: next c tiles, or fo gather on the last stage
        if (c < 3) {
#pragma unroll
            for (int j = 0; j < 4; ++j) {
                xr[j] = *(const float4*)(x + (((size_t)row * NN + n) * 4 + (c + 1)) * 128 + q * 16 + j * 4);
                fr[j] = *(const float4*)(f + (((size_t)(c + 1) * NN + n) * 64 + row) * 128 + q * 16 + j * 4);
            }
        } else {
            const float* fob = fo + (size_t)n * 8192 + (t >> 2);
            const int rbase = (t & 3) * 16;
#pragma unroll
            for (int u = 0; u < 16; ++u) fov[u] = fob[(rbase + u) * 128];
        }

        // projection MMAs: 16b x 16r per warp, K=128, 3 split terms
#pragma unroll
        for (int kk = 0; kk < 8; ++kk) {
            uint32_t ah[4], al[4];
            const uint32_t ab = (uint32_t)((bb + g) * 272 + kk * 32 + tg * 4);
            ah[0] = *(const uint32_t*)(buf + XH + ab);
            ah[1] = *(const uint32_t*)(buf + XH + ab + 2176);
            ah[2] = *(const uint32_t*)(buf + XH + ab + 16);
            ah[3] = *(const uint32_t*)(buf + XH + ab + 2192);
            al[0] = *(const uint32_t*)(buf + XL + ab);
            al[1] = *(const uint32_t*)(buf + XL + ab + 2176);
            al[2] = *(const uint32_t*)(buf + XL + ab + 16);
            al[3] = *(const uint32_t*)(buf + XL + ab + 2192);
#pragma unroll
            for (int nt = 0; nt < 2; ++nt) {
                uint32_t bh[2], bl[2];
                const uint32_t bby = (uint32_t)((wr * 16 + nt * 8 + g) * 272 + kk * 32 + tg * 4);
                bh[0] = *(const uint32_t*)(buf + FH + bby);
                bh[1] = *(const uint32_t*)(buf + FH + bby + 16);
                bl[0] = *(const uint32_t*)(buf + FL + bby);
                bl[1] = *(const uint32_t*)(buf + FL + bby + 16);
                mma_bf16(acc[c][nt], ah, bh);
                mma_bf16(acc[c][nt], ah, bl);
                mma_bf16(acc[c][nt], al, bh);
            }
        }
    }

    // ---- RMS partials over this warp's 16-r slice ----
#pragma unroll
    for (int c = 0; c < 4; ++c) {
        float s0 = 0.f, s1 = 0.f;
#pragma unroll
        for (int nt = 0; nt < 2; ++nt) {
            s0 = fmaf(acc[c][nt][0], acc[c][nt][0], s0);
            s0 = fmaf(acc[c][nt][1], acc[c][nt][1], s0);
            s1 = fmaf(acc[c][nt][2], acc[c][nt][2], s1);
            s1 = fmaf(acc[c][nt][3], acc[c][nt][3], s1);
        }
        s0 += __shfl_xor_sync(0xffffffffu, s0, 1);
        s0 += __shfl_xor_sync(0xffffffffu, s0, 2);
        s1 += __shfl_xor_sync(0xffffffffu, s1, 1);
        s1 += __shfl_xor_sync(0xffffffffu, s1, 2);
        if (tg == 0) {
            *(float*)(sm + SS_OFF + ((c * 4 + wr) * 64 + bb + g) * 4)     = s0;
            *(float*)(sm + SS_OFF + ((c * 4 + wr) * 64 + bb + g + 8) * 4) = s1;
        }
    }

    // ---- fo^T STS (buffer 0 region FOH/FOL; stage-2 MMAs long done) ----
    {
        const int o = t >> 2, rbase = (t & 3) * 16;
#pragma unroll
        for (int u = 0; u < 8; ++u) {
            uint32_t hi, lo;
            split2(fov[2 * u], fov[2 * u + 1], hi, lo);
            *(uint32_t*)(sm + FOH_OFF + o * 144 + (rbase + 2 * u) * 2) = hi;
            *(uint32_t*)(sm + FOL_OFF + o * 144 + (rbase + 2 * u) * 2) = lo;
        }
    }
    __syncthreads();

    if (t < 64) {
        float prod = gn;
#pragma unroll
        for (int c = 0; c < 4; ++c) {
            float s = 0.f;
#pragma unroll
            for (int w = 0; w < 4; ++w)
                s += *(const float*)(sm + SS_OFF + ((c * 4 + w) * 64 + t) * 4);
            prod *= rsqrtf(s * 0.015625f + 1e-6f);
        }
        *(float*)(sm + RINV_OFF + t * 4) = prod;
    }
    __syncthreads();

    // ---- merged = prod_c P * rinvprod -> bf16 hi/lo [b][r] ----
    {
        const float r0v = *(const float*)(sm + RINV_OFF + (bb + g) * 4);
        const float r1v = *(const float*)(sm + RINV_OFF + (bb + g + 8) * 4);
#pragma unroll
        for (int nt = 0; nt < 2; ++nt) {
            const int rc = wr * 16 + nt * 8 + tg * 2;
            float m0 = acc[0][nt][0] * acc[1][nt][0] * acc[2][nt][0] * acc[3][nt][0] * r0v;
            float m1 = acc[0][nt][1] * acc[1][nt][1] * acc[2][nt][1] * acc[3][nt][1] * r0v;
            float m2 = acc[0][nt][2] * acc[1][nt][2] * acc[2][nt][2] * acc[3][nt][2] * r1v;
            float m3 = acc[0][nt][3] * acc[1][nt][3] * acc[2][nt][3] * acc[3][nt][3] * r1v;
            uint32_t h01, l01, h23, l23;
            split2(m0, m1, h01, l01);
            split2(m2, m3, h23, l23);
            *(uint32_t*)(sm + MH_OFF + (bb + g) * 144 + rc * 2)     = h01;
            *(uint32_t*)(sm + ML_OFF + (bb + g) * 144 + rc * 2)     = l01;
            *(uint32_t*)(sm + MH_OFF + (bb + g + 8) * 144 + rc * 2) = h23;
            *(uint32_t*)(sm + ML_OFF + (bb + g + 8) * 144 + rc * 2) = l23;
        }
    }
    __syncthreads();

    // ---- output GEMM: warp (wb, wo=wr): 16b x 32o, K=64, 3 terms ----
    float acc2[4][4];
#pragma unroll
    for (int nt = 0; nt < 4; ++nt)
#pragma unroll
        for (int u = 0; u < 4; ++u) acc2[nt][u] = 0.0f;

#pragma unroll
    for (int kk = 0; kk < 4; ++kk) {
        uint32_t ah[4], al[4];
        const uint32_t ab = (uint32_t)((bb + g) * 144 + kk * 32 + tg * 4);
        ah[0] = *(const uint32_t*)(sm + MH_OFF + ab);
        ah[1] = *(const uint32_t*)(sm + MH_OFF + ab + 1152);
        ah[2] = *(const uint32_t*)(sm + MH_OFF + ab + 16);
        ah[3] = *(const uint32_t*)(sm + MH_OFF + ab + 1168);
        al[0] = *(const uint32_t*)(sm + ML_OFF + ab);
        al[1] = *(const uint32_t*)(sm + ML_OFF + ab + 1152);
        al[2] = *(const uint32_t*)(sm + ML_OFF + ab + 16);
        al[3] = *(const uint32_t*)(sm + ML_OFF + ab + 1168);
#pragma unroll
        for (int nt = 0; nt < 4; ++nt) {
            uint32_t bh[2], bl[2];
            const uint32_t bby = (uint32_t)((wr * 32 + nt * 8 + g) * 144 + kk * 32 + tg * 4);
            bh[0] = *(const uint32_t*)(sm + FOH_OFF + bby);
            bh[1] = *(const uint32_t*)(sm + FOH_OFF + bby + 16);
            bl[0] = *(const uint32_t*)(sm + FOL_OFF + bby);
            bl[1] = *(const uint32_t*)(sm + FOL_OFF + bby + 16);
            mma_bf16(acc2[nt], ah, bh);
            mma_bf16(acc2[nt], ah, bl);
            mma_bf16(acc2[nt], al, bh);
        }
    }

    // ---- store with residual mean ----
#pragma unroll
    for (int nt = 0; nt < 4; ++nt) {
        const int oc = wr * 32 + nt * 8 + tg * 2;
        const int b0 = bb + g, b1 = bb + g + 8;
        const float2 r0 = *(const float2*)(sm + RES_OFF + (b0 * 128 + oc) * 4);
        const float2 r1 = *(const float2*)(sm + RES_OFF + (b1 * 128 + oc) * 4);
        float2 o0, o1;
        o0.x = acc2[nt][0] + 0.25f * r0.x;
        o0.y = acc2[nt][1] + 0.25f * r0.y;
        o1.x = acc2[nt][2] + 0.25f * r1.x;
        o1.y = acc2[nt][3] + 0.25f * r1.y;
        *(float2*)(out + ((size_t)b0 * NN + n) * 128 + oc) = o0;
        *(float2*)(out + ((size_t)b1 * NN + n) * 128 + oc) = o1;
    }
}

extern "C" void kernel_launch(void* const* d_in, const int* in_sizes, int n_in,
                              void* d_out, int out_size)
{
    const float* x       = (const float*)d_in[0];
    const float* factors = (const float*)d_in[1];
    const float* fo      = (const float*)d_in[2];
    const float* gain    = (const float*)d_in[3];
    float* out = (float*)d_out;

    cudaFuncSetAttribute(cpquad_mma2, cudaFuncAttributeMaxDynamicSharedMemorySize, SMEM_BYTES);
    cpquad_mma2<<<NN, 512, SMEM_BYTES>>>(x, factors, fo, gain, out);
}

// round 6
// speedup vs baseline: 1.2172x; 1.2172x over previous
#include <cuda_runtime.h>
#include <cuda_bf16.h>
#include <stdint.h>

// CPQuadRankLayer via mma.sync bf16 3-term split. B=64, N=1024, C=4, R=64, D=O=128.
// 256 threads, 2 CTAs/SM (cross-CTA phase overlap), warp tile 16b x 32r.
//   P_c[b][r] = sum_i x[b,n,c,i] f[c,n,r,i]
//   p = P / rms_r(P); merged = prod_c p * gain; out = merged @ fo + 0.25*sum_c x

#define NN 1024

// smem byte offsets
#define XH_OFF   0        // 64 rows x 272B (128 bf16 + pad)
#define XL_OFF   17408
#define FH_OFF   34816
#define FL_OFF   52224
#define RES_OFF  69632    // res[b][o] f32 accum: 64*128*4 = 32768
#define SS_OFF   102400   // ss[2][4][64] f32 = 2048
#define RINV_OFF 104448   // 64 f32
#define SMEM_BYTES 104704 // <= 113.5KB -> 2 CTAs/SM
// epilogue overlay (over X/F region)
#define MH_OFF   0        // merged hi: 64 rows x 144B
#define ML_OFF   9216
#define FOH_OFF  18432    // fo^T hi: 128 rows x 144B
#define FOL_OFF  36864

__device__ __forceinline__ void split2(float a, float b, uint32_t& hi, uint32_t& lo) {
    __nv_bfloat16 ah = __float2bfloat16(a), bh = __float2bfloat16(b);
    hi = ((uint32_t)__bfloat16_as_ushort(bh) << 16) | (uint32_t)__bfloat16_as_ushort(ah);
    __nv_bfloat16 al = __float2bfloat16(a - __bfloat162float(ah));
    __nv_bfloat16 bl = __float2bfloat16(b - __bfloat162float(bh));
    lo = ((uint32_t)__bfloat16_as_ushort(bl) << 16) | (uint32_t)__bfloat16_as_ushort(al);
}

__device__ __forceinline__ void mma_bf16(float* c, const uint32_t* a, const uint32_t* b) {
    asm volatile(
        "mma.sync.aligned.m16n8k16.row.col.f32.bf16.bf16.f32 "
        "{%0,%1,%2,%3}, {%4,%5,%6,%7}, {%8,%9}, {%0,%1,%2,%3};"
        : "+f"(c[0]), "+f"(c[1]), "+f"(c[2]), "+f"(c[3])
        : "r"(a[0]), "r"(a[1]), "r"(a[2]), "r"(a[3]), "r"(b[0]), "r"(b[1]));
}

__global__ __launch_bounds__(256, 2)
void cpquad_mma3(const float* __restrict__ x, const float* __restrict__ f,
                 const float* __restrict__ fo, const float* __restrict__ gain,
                 float* __restrict__ out)
{
    extern __shared__ char sm[];
    const int n = blockIdx.x;
    const int t = threadIdx.x;
    const int lane = t & 31, wid = t >> 5;
    const int g = lane >> 2, tg = lane & 3;
    const int wb = wid >> 1, ws = wid & 1;   // b-tile (16 rows), r-half (32)
    const int bb = wb * 16;
    const float gn = __ldg(&gain[n]);

    float4 xr[8];
    float acc[4][4][4];
#pragma unroll
    for (int c = 0; c < 4; ++c)
#pragma unroll
        for (int nt = 0; nt < 4; ++nt)
#pragma unroll
            for (int u = 0; u < 4; ++u) acc[c][nt][u] = 0.0f;

    // prologue LDG x(0): thread rows {wid+8j}, float4 col = lane
#pragma unroll
    for (int j = 0; j < 8; ++j)
        xr[j] = *(const float4*)(x + (((size_t)(j * 8 + wid) * NN + n) * 4 + 0) * 128 + lane * 4);

#pragma unroll
    for (int c = 0; c < 4; ++c) {
        // issue f(c) LDGs early, then x STS + residual RMW while f is in flight
        float4 fr[8];
#pragma unroll
        for (int j = 0; j < 8; ++j)
            fr[j] = *(const float4*)(f + (((size_t)c * NN + n) * 64 + (j * 8 + wid)) * 128 + lane * 4);

#pragma unroll
        for (int j = 0; j < 8; ++j) {
            const int row = j * 8 + wid;
            uint2 hi, lo;
            split2(xr[j].x, xr[j].y, hi.x, lo.x);
            split2(xr[j].z, xr[j].w, hi.y, lo.y);
            *(uint2*)(sm + XH_OFF + row * 272 + lane * 8) = hi;
            *(uint2*)(sm + XL_OFF + row * 272 + lane * 8) = lo;
            // residual accumulation in smem (f32)
            float4* rp = (float4*)(sm + RES_OFF + row * 512 + lane * 16);
            if (c == 0) *rp = xr[j];
            else {
                float4 o = *rp;
                o.x += xr[j].x; o.y += xr[j].y; o.z += xr[j].z; o.w += xr[j].w;
                *rp = o;
            }
        }
#pragma unroll
        for (int j = 0; j < 8; ++j) {
            const int row = j * 8 + wid;
            uint2 hi, lo;
            split2(fr[j].x, fr[j].y, hi.x, lo.x);
            split2(fr[j].z, fr[j].w, hi.y, lo.y);
            *(uint2*)(sm + FH_OFF + row * 272 + lane * 8) = hi;
            *(uint2*)(sm + FL_OFF + row * 272 + lane * 8) = lo;
        }
        __syncthreads();

        // prefetch x(c+1): latency hides under the MMA block
        if (c < 3) {
#pragma unroll
            for (int j = 0; j < 8; ++j)
                xr[j] = *(const float4*)(x + (((size_t)(j * 8 + wid) * NN + n) * 4 + (c + 1)) * 128 + lane * 4);
        }

        // projection MMAs: 16b x 32r per warp, K=128 (8 k16-steps), 3 split terms
#pragma unroll
        for (int kk = 0; kk < 8; ++kk) {
            uint32_t ah[4], al[4];
            const uint32_t ab = (uint32_t)((bb + g) * 272 + kk * 32 + tg * 4);
            ah[0] = *(const uint32_t*)(sm + XH_OFF + ab);
            ah[1] = *(const uint32_t*)(sm + XH_OFF + ab + 2176);
            ah[2] = *(const uint32_t*)(sm + XH_OFF + ab + 16);
            ah[3] = *(const uint32_t*)(sm + XH_OFF + ab + 2192);
            al[0] = *(const uint32_t*)(sm + XL_OFF + ab);
            al[1] = *(const uint32_t*)(sm + XL_OFF + ab + 2176);
            al[2] = *(const uint32_t*)(sm + XL_OFF + ab + 16);
            al[3] = *(const uint32_t*)(sm + XL_OFF + ab + 2192);
#pragma unroll
            for (int nt = 0; nt < 4; ++nt) {
                uint32_t bh[2], bl[2];
                const uint32_t bby = (uint32_t)((ws * 32 + nt * 8 + g) * 272 + kk * 32 + tg * 4);
                bh[0] = *(const uint32_t*)(sm + FH_OFF + bby);
                bh[1] = *(const uint32_t*)(sm + FH_OFF + bby + 16);
                bl[0] = *(const uint32_t*)(sm + FL_OFF + bby);
                bl[1] = *(const uint32_t*)(sm + FL_OFF + bby + 16);
                mma_bf16(acc[c][nt], ah, bh);
                mma_bf16(acc[c][nt], ah, bl);
                mma_bf16(acc[c][nt], al, bh);
            }
        }
        __syncthreads();
    }

    // ---- RMS partials: lane rows g, g+8; reduce over the 4 tg lanes ----
#pragma unroll
    for (int c = 0; c < 4; ++c) {
        float s0 = 0.f, s1 = 0.f;
#pragma unroll
        for (int nt = 0; nt < 4; ++nt) {
            s0 = fmaf(acc[c][nt][0], acc[c][nt][0], s0);
            s0 = fmaf(acc[c][nt][1], acc[c][nt][1], s0);
            s1 = fmaf(acc[c][nt][2], acc[c][nt][2], s1);
            s1 = fmaf(acc[c][nt][3], acc[c][nt][3], s1);
        }
        s0 += __shfl_xor_sync(0xffffffffu, s0, 1);
        s0 += __shfl_xor_sync(0xffffffffu, s0, 2);
        s1 += __shfl_xor_sync(0xffffffffu, s1, 1);
        s1 += __shfl_xor_sync(0xffffffffu, s1, 2);
        if (tg == 0) {
            *(float*)(sm + SS_OFF + (((ws * 4 + c) * 64) + bb + g) * 4)     = s0;
            *(float*)(sm + SS_OFF + (((ws * 4 + c) * 64) + bb + g + 8) * 4) = s1;
        }
    }
    __syncthreads();

    // rinv-product per b (first 64 threads) + fo^T staging (all threads)
    if (t < 64) {
        float prod = gn;
#pragma unroll
        for (int c = 0; c < 4; ++c) {
            float s = *(const float*)(sm + SS_OFF + ((0 * 4 + c) * 64 + t) * 4)
                    + *(const float*)(sm + SS_OFF + ((1 * 4 + c) * 64 + t) * 4);
            prod *= rsqrtf(s * 0.015625f + 1e-6f);
        }
        *(float*)(sm + RINV_OFF + t * 4) = prod;
    }
    {
        const int o = t >> 1, rh = (t & 1) * 32;
        const float* fob = fo + (size_t)n * 8192 + o;
#pragma unroll
        for (int u = 0; u < 8; ++u) {
            const int r0 = rh + u * 4;
            float v0 = fob[(r0 + 0) * 128], v1 = fob[(r0 + 1) * 128];
            float v2 = fob[(r0 + 2) * 128], v3 = fob[(r0 + 3) * 128];
            uint2 hi, lo;
            split2(v0, v1, hi.x, lo.x);
            split2(v2, v3, hi.y, lo.y);
            *(uint2*)(sm + FOH_OFF + o * 144 + r0 * 2) = hi;
            *(uint2*)(sm + FOL_OFF + o * 144 + r0 * 2) = lo;
        }
    }
    __syncthreads();

    // merged = prod_c P * rinvprod  -> bf16 hi/lo tile [b][r]
    {
        const float r0v = *(const float*)(sm + RINV_OFF + (bb + g) * 4);
        const float r1v = *(const float*)(sm + RINV_OFF + (bb + g + 8) * 4);
#pragma unroll
        for (int nt = 0; nt < 4; ++nt) {
            const int rc = ws * 32 + nt * 8 + tg * 2;
            float m0 = acc[0][nt][0] * acc[1][nt][0] * acc[2][nt][0] * acc[3][nt][0] * r0v;
            float m1 = acc[0][nt][1] * acc[1][nt][1] * acc[2][nt][1] * acc[3][nt][1] * r0v;
            float m2 = acc[0][nt][2] * acc[1][nt][2] * acc[2][nt][2] * acc[3][nt][2] * r1v;
            float m3 = acc[0][nt][3] * acc[1][nt][3] * acc[2][nt][3] * acc[3][nt][3] * r1v;
            uint32_t h01, l01, h23, l23;
            split2(m0, m1, h01, l01);
            split2(m2, m3, h23, l23);
            *(uint32_t*)(sm + MH_OFF + (bb + g) * 144 + rc * 2)     = h01;
            *(uint32_t*)(sm + ML_OFF + (bb + g) * 144 + rc * 2)     = l01;
            *(uint32_t*)(sm + MH_OFF + (bb + g + 8) * 144 + rc * 2) = h23;
            *(uint32_t*)(sm + ML_OFF + (bb + g + 8) * 144 + rc * 2) = l23;
        }
    }
    __syncthreads();

    // output GEMM: warp = (wb, o-half ws): 16b x 64o, K=64 (4 k16-steps), 3 terms
    float acc2[8][4];
#pragma unroll
    for (int nt = 0; nt < 8; ++nt)
#pragma unroll
        for (int u = 0; u < 4; ++u) acc2[nt][u] = 0.0f;

    const int obase = ws * 64;
#pragma unroll
    for (int kk = 0; kk < 4; ++kk) {
        uint32_t ah[4], al[4];
        const uint32_t ab = (uint32_t)((bb + g) * 144 + kk * 32 + tg * 4);
        ah[0] = *(const uint32_t*)(sm + MH_OFF + ab);
        ah[1] = *(const uint32_t*)(sm + MH_OFF + ab + 1152);
        ah[2] = *(const uint32_t*)(sm + MH_OFF + ab + 16);
        ah[3] = *(const uint32_t*)(sm + MH_OFF + ab + 1168);
        al[0] = *(const uint32_t*)(sm + ML_OFF + ab);
        al[1] = *(const uint32_t*)(sm + ML_OFF + ab + 1152);
        al[2] = *(const uint32_t*)(sm + ML_OFF + ab + 16);
        al[3] = *(const uint32_t*)(sm + ML_OFF + ab + 1168);
#pragma unroll
        for (int nt = 0; nt < 8; ++nt) {
            uint32_t bh[2], bl[2];
            const uint32_t bby = (uint32_t)((obase + nt * 8 + g) * 144 + kk * 32 + tg * 4);
            bh[0] = *(const uint32_t*)(sm + FOH_OFF + bby);
            bh[1] = *(const uint32_t*)(sm + FOH_OFF + bby + 16);
            bl[0] = *(const uint32_t*)(sm + FOL_OFF + bby);
            bl[1] = *(const uint32_t*)(sm + FOL_OFF + bby + 16);
            mma_bf16(acc2[nt], ah, bh);
            mma_bf16(acc2[nt], ah, bl);
            mma_bf16(acc2[nt], al, bh);
        }
    }

    // store with residual mean (res read from smem accumulator)
#pragma unroll
    for (int nt = 0; nt < 8; ++nt) {
        const int oc = obase + nt * 8 + tg * 2;
        const int b0 = bb + g, b1 = bb + g + 8;
        const float2 r0 = *(const float2*)(sm + RES_OFF + (b0 * 128 + oc) * 4);
        const float2 r1 = *(const float2*)(sm + RES_OFF + (b1 * 128 + oc) * 4);
        float2 o0, o1;
        o0.x = acc2[nt][0] + 0.25f * r0.x;
        o0.y = acc2[nt][1] + 0.25f * r0.y;
        o1.x = acc2[nt][2] + 0.25f * r1.x;
        o1.y = acc2[nt][3] + 0.25f * r1.y;
        *(float2*)(out + ((size_t)b0 * NN + n) * 128 + oc) = o0;
        *(float2*)(out + ((size_t)b1 * NN + n) * 128 + oc) = o1;
    }
}

extern "C" void kernel_launch(void* const* d_in, const int* in_sizes, int n_in,
                              void* d_out, int out_size)
{
    const float* x       = (const float*)d_in[0];
    const float* factors = (const float*)d_in[1];
    const float* fo      = (const float*)d_in[2];
    const float* gain    = (const float*)d_in[3];
    float* out = (float*)d_out;

    cudaFuncSetAttribute(cpquad_mma3, cudaFuncAttributeMaxDynamicSharedMemorySize, SMEM_BYTES);
    cpquad_mma3<<<NN, 256, SMEM_BYTES>>>(x, factors, fo, gain, out);
}